// round 15
// baseline (speedup 1.0000x reference)
#include <cuda_runtime.h>
#include <cuda_fp16.h>
#include <cstdint>

// ---------------------------------------------------------------------------
// Problem constants
// ---------------------------------------------------------------------------
#define BATCH   2048
#define NTOK    49
#define HEADS   16
#define HDIM    32
#define CDIM    512
#define MW      64
#define MTOT    (BATCH*NTOK)   // 100352
#define QKVCOLS (3*CDIM)       // 1536

// head-major q/k/v: [b][h][n][d]
__device__ float g_q[(size_t)BATCH * HEADS * NTOK * HDIM];
__device__ float g_k[(size_t)BATCH * HEADS * NTOK * HDIM];
__device__ float g_v[(size_t)BATCH * HEADS * NTOK * HDIM];
__device__ __half g_ah[(size_t)MTOT * CDIM];     // hidden fp16
__device__ __half g_wh[(size_t)QKVCOLS * CDIM];  // weights fp16 (q|k|v rows)

// ---------------------------------------------------------------------------
// helpers
// ---------------------------------------------------------------------------
__device__ __forceinline__ uint32_t smem_u32(const void* p) {
    uint32_t a;
    asm("{ .reg .u64 t; cvta.to.shared.u64 t, %1; cvt.u32.u64 %0, t; }" : "=r"(a) : "l"(p));
    return a;
}
__device__ __forceinline__ void cp16(uint32_t saddr, const void* gaddr) {
    asm volatile("cp.async.cg.shared.global [%0], [%1], 16;" :: "r"(saddr), "l"(gaddr) : "memory");
}
__device__ __forceinline__ void cp_commit() {
    asm volatile("cp.async.commit_group;" ::: "memory");
}
template<int N> __device__ __forceinline__ void cp_wait() {
    asm volatile("cp.async.wait_group %0;" :: "n"(N) : "memory");
}
#define LDX4(d, addr) \
    asm volatile("ldmatrix.sync.aligned.m8n8.x4.shared.b16 {%0,%1,%2,%3}, [%4];" \
        : "=r"((d)[0]), "=r"((d)[1]), "=r"((d)[2]), "=r"((d)[3]) : "r"(addr))

__device__ __forceinline__ void mma_f16(float* c, const uint32_t* a, uint32_t b0, uint32_t b1) {
    asm volatile(
        "mma.sync.aligned.m16n8k16.row.col.f32.f16.f16.f32 "
        "{%0,%1,%2,%3}, {%4,%5,%6,%7}, {%8,%9}, {%0,%1,%2,%3};"
        : "+f"(c[0]), "+f"(c[1]), "+f"(c[2]), "+f"(c[3])
        : "r"(a[0]), "r"(a[1]), "r"(a[2]), "r"(a[3]), "r"(b0), "r"(b1));
}

// ---------------------------------------------------------------------------
// Prep (single launch): fp32 -> fp16, hidden + all three weight matrices.
// ---------------------------------------------------------------------------
#define NH8 (MTOT * CDIM / 8)
#define NW8 32768

__global__ __launch_bounds__(256) void prep(
    const float* __restrict__ hidden,
    const float* __restrict__ wq, const float* __restrict__ wk,
    const float* __restrict__ wv,
    __half* __restrict__ ah, __half* __restrict__ wh)
{
    const int i = blockIdx.x * 256 + threadIdx.x;
    const float* src;
    __half* dst;
    int j;
    if (i < NH8) { src = hidden; dst = ah; j = i; }
    else {
        const int t = i - NH8;
        if (t >= 3 * NW8) return;
        const int m = t >> 15;
        j = t & (NW8 - 1);
        src = (m == 0) ? wq : (m == 1) ? wk : wv;
        dst = wh + (size_t)m * 512 * CDIM;
    }
    const float4 v0 = ((const float4*)src)[(size_t)j * 2];
    const float4 v1 = ((const float4*)src)[(size_t)j * 2 + 1];
    const float vv[8] = {v0.x, v0.y, v0.z, v0.w, v1.x, v1.y, v1.z, v1.w};
    __half h[8];
#pragma unroll
    for (int e = 0; e < 8; ++e) h[e] = __float2half_rn(vv[e]);
    *(uint4*)(dst + (size_t)j * 8) = *(const uint4*)h;
}

// steering no-op: [init,init,prep,dummy,gemm,attn] -> ncu -s 5 captures attn
__global__ void dummy_k() {}

// ---------------------------------------------------------------------------
// Tensor-core QKV GEMM — unchanged from R13 (head-major epilogue)
// ---------------------------------------------------------------------------
#define GBM 128
#define GBN 128
#define GBK 32
#define ASTR 40
#define STAGE_H (2 * GBM * ASTR)
#define OFF_AH 0
#define OFF_BH (GBM * ASTR)
#define NSTAGE 4
#define GSMEM  (NSTAGE * STAGE_H * 2)   // 81920 bytes

__global__ __launch_bounds__(256, 2) void qkv_gemm_mma(
    const __half* __restrict__ ah, const __half* __restrict__ wh,
    const float* __restrict__ bq, const float* __restrict__ bk2,
    const float* __restrict__ bv)
{
    extern __shared__ __align__(16) __half sm[];
    const uint32_t sb = smem_u32(sm);
    const int tid  = threadIdx.x;
    const int lane = tid & 31;
    const int w    = tid >> 5;
    const int m0   = blockIdx.y * GBM;
    const int jg0  = blockIdx.x * GBN;

    const int row = tid >> 1;
    const int c0  = (tid & 1) * 2;

    const __half* gah = ah + (size_t)m0 * CDIM;
    const __half* gwh = wh + (size_t)jg0 * CDIM;

    auto issue = [&](int it) {
        const uint32_t bufb = sb + (uint32_t)((it & 3) * STAGE_H) * 2;
        const size_t   gr = (size_t)row * CDIM + it * GBK;
        const uint32_t sr = (uint32_t)(row * ASTR) * 2;
#pragma unroll
        for (int c = 0; c < 2; ++c) {
            const int ch = c0 + c;
            cp16(bufb + OFF_AH * 2 + sr + ch * 16, gah + gr + ch * 8);
            cp16(bufb + OFF_BH * 2 + sr + ch * 16, gwh + gr + ch * 8);
        }
    };

    const int wm = (w & 1) * 64;
    const int wn = (w >> 1) * 32;
    const int lr = lane & 15;
    const int lc = (lane >> 4) * 8;

    float acc[4][4][4];
#pragma unroll
    for (int mi = 0; mi < 4; ++mi)
#pragma unroll
        for (int ni = 0; ni < 4; ++ni)
#pragma unroll
            for (int e = 0; e < 4; ++e) acc[mi][ni][e] = 0.f;

    auto compute = [&](int p) {
        const uint32_t bufb = sb + (uint32_t)(p * STAGE_H) * 2;
#pragma unroll
        for (int ks = 0; ks < 2; ++ks) {
            const int k0 = ks * 16;
            uint32_t AH[4][4], BH[2][4];
#pragma unroll
            for (int mi = 0; mi < 4; ++mi) {
                const uint32_t aoff = bufb + (uint32_t)((wm + mi * 16 + lr) * ASTR + k0 + lc) * 2;
                LDX4(AH[mi], aoff + OFF_AH * 2);
            }
#pragma unroll
            for (int nb = 0; nb < 2; ++nb) {
                const uint32_t boff = bufb + (uint32_t)((wn + nb * 16 + lr) * ASTR + k0 + lc) * 2;
                LDX4(BH[nb], boff + OFF_BH * 2);
            }
#pragma unroll
            for (int mi = 0; mi < 4; ++mi)
#pragma unroll
                for (int ni = 0; ni < 4; ++ni) {
                    const int nb = ni >> 1, sel = ni & 1;
                    mma_f16(acc[mi][ni], AH[mi], BH[nb][sel], BH[nb][sel + 2]);
                }
        }
    };

    issue(0); cp_commit();
    issue(1); cp_commit();
    issue(2); cp_commit();

#pragma unroll 1
    for (int it = 0; it < 13; ++it) {
        cp_wait<2>();
        __syncthreads();
        issue(it + 3);
        cp_commit();
        compute(it & 3);
    }
    cp_wait<2>(); __syncthreads(); compute(13 & 3);
    cp_wait<1>(); __syncthreads(); compute(14 & 3);
    cp_wait<0>(); __syncthreads(); compute(15 & 3);

    const int tsel = jg0 >> 9;
    float* gout = (tsel == 0) ? g_q : (tsel == 1) ? g_k : g_v;
    const float* bptr = (tsel == 0) ? bq : (tsel == 1) ? bk2 : bv;

#pragma unroll
    for (int ni = 0; ni < 4; ++ni) {
        const int jg = jg0 + wn + ni * 8 + 2 * (lane & 3);
        const int c  = jg & 511;
        const int h  = c >> 5;
        const int d  = c & 31;
        const float b0v = bptr[c];
        const float b1v = bptr[c + 1];
#pragma unroll
        for (int mi = 0; mi < 4; ++mi) {
#pragma unroll
            for (int half = 0; half < 2; ++half) {
                const int r = m0 + wm + mi * 16 + (lane >> 2) + half * 8;
                const int b = r / NTOK;
                const int n = r - b * NTOK;
                const size_t idx = (((size_t)(b * HEADS + h)) * NTOK + n) * HDIM + d;
                float2 o = { acc[mi][ni][half * 2 + 0] + b0v,
                             acc[mi][ni][half * 2 + 1] + b1v };
                *(float2*)&gout[idx] = o;
            }
        }
    }
}

// ---------------------------------------------------------------------------
// Attention per (window b, head h):
//   scores 4x4 reg-tiled -> sc; softmax writes PROBS back to sc;
//   PV as second 4x4 reg-tiled smem GEMM (no shuffles).
// ---------------------------------------------------------------------------
#define ROWP 36
#define SCP  52   // float4-aligned prob/score row stride

__global__ __launch_bounds__(128) void attn(
    const float* __restrict__ mask,
    const float* __restrict__ bias_table,
    float* __restrict__ out)
{
    __shared__ __align__(16) float qs[NTOK * ROWP];
    __shared__ __align__(16) float ks[NTOK * ROWP];
    __shared__ __align__(16) float vs[NTOK * ROWP];
    __shared__ __align__(16) float sc[NTOK * SCP];

    const int tid = threadIdx.x;
    const int bh  = blockIdx.x;
    const int b   = bh >> 4;
    const int h   = bh & 15;

    // ---- contiguous loads from head-major layout
    const size_t hbase = (size_t)bh * NTOK * HDIM;
    const float* qg = g_q + hbase;
    const float* kg = g_k + hbase;
    const float* vg = g_v + hbase;
    for (int t = tid; t < NTOK * 8; t += 128) {
        const int n = t >> 3, f = t & 7;
        const int go = n * HDIM + f * 4;
        *(float4*)&qs[n * ROWP + f * 4] = *(const float4*)(qg + go);
        *(float4*)&ks[n * ROWP + f * 4] = *(const float4*)(kg + go);
        *(float4*)&vs[n * ROWP + f * 4] = *(const float4*)(vg + go);
    }
    __syncthreads();

    // ---- scores, 4x4 tiles (13x13 = 169 tasks)
    const float* mrow = mask + (size_t)(b & (MW - 1)) * (NTOK * NTOK);
    for (int t = tid; t < 169; t += 128) {
        const int ti = t / 13, tj = t - ti * 13;
        const int i0 = ti * 4, j0 = tj * 4;
        int ii[4], jj[4];
#pragma unroll
        for (int r = 0; r < 4; ++r) {
            ii[r] = (i0 + r < NTOK) ? i0 + r : NTOK - 1;
            jj[r] = (j0 + r < NTOK) ? j0 + r : NTOK - 1;
        }
        float a[4][4];
#pragma unroll
        for (int r = 0; r < 4; ++r)
#pragma unroll
            for (int c = 0; c < 4; ++c) a[r][c] = 0.f;
#pragma unroll
        for (int dg = 0; dg < 8; ++dg) {
            float4 q4[4], k4[4];
#pragma unroll
            for (int r = 0; r < 4; ++r) {
                q4[r] = *(const float4*)&qs[ii[r] * ROWP + dg * 4];
                k4[r] = *(const float4*)&ks[jj[r] * ROWP + dg * 4];
            }
#pragma unroll
            for (int r = 0; r < 4; ++r)
#pragma unroll
                for (int c = 0; c < 4; ++c)
                    a[r][c] += q4[r].x * k4[c].x + q4[r].y * k4[c].y
                             + q4[r].z * k4[c].z + q4[r].w * k4[c].w;
        }
        const float sca = 0.17677669529663687f;   // 1/sqrt(32)
#pragma unroll
        for (int r = 0; r < 4; ++r) {
            const int iiv = i0 + r;
            if (iiv >= NTOK) break;
            const int iy = iiv / 7, ix = iiv - iy * 7;
#pragma unroll
            for (int c = 0; c < 4; ++c) {
                const int jjv = j0 + c;
                if (jjv >= NTOK) break;
                const int jy = jjv / 7, jx = jjv - jy * 7;
                const int ridx = (iy - jy + 6) * 13 + (ix - jx + 6);
                float s = a[r][c] * sca;
                s += bias_table[ridx * HEADS + h];
                s += mrow[iiv * NTOK + jjv];
                sc[iiv * SCP + jjv] = s;
            }
        }
    }
    __syncthreads();

    // ---- softmax: 2 rows per warp pass, probs written back into sc
    const int warp = tid >> 5;
    const int lane = tid & 31;
    for (int pr = warp; pr < 25; pr += 4) {
        const int r0 = pr * 2;
        const int r1 = r0 + 1;
        const bool has1 = (r1 < NTOK);

        const float sA0 = sc[r0 * SCP + lane];
        const float sA1 = (lane < 17) ? sc[r0 * SCP + 32 + lane] : -3.4e38f;
        const float sB0 = has1 ? sc[r1 * SCP + lane] : 0.f;
        const float sB1 = (has1 && lane < 17) ? sc[r1 * SCP + 32 + lane] : -3.4e38f;

        float mA = fmaxf(sA0, sA1);
        float mB = fmaxf(sB0, sB1);
#pragma unroll
        for (int o = 16; o > 0; o >>= 1) {
            mA = fmaxf(mA, __shfl_xor_sync(0xffffffffu, mA, o));
            mB = fmaxf(mB, __shfl_xor_sync(0xffffffffu, mB, o));
        }
        const float eA0 = __expf(sA0 - mA);
        const float eA1 = (lane < 17) ? __expf(sA1 - mA) : 0.f;
        const float eB0 = __expf(sB0 - mB);
        const float eB1 = (lane < 17) ? __expf(sB1 - mB) : 0.f;
        float sumA = eA0 + eA1, sumB = eB0 + eB1;
#pragma unroll
        for (int o = 16; o > 0; o >>= 1) {
            sumA += __shfl_xor_sync(0xffffffffu, sumA, o);
            sumB += __shfl_xor_sync(0xffffffffu, sumB, o);
        }
        const float invA = __frcp_rn(sumA);
        const float invB = __frcp_rn(sumB);

        sc[r0 * SCP + lane] = eA0 * invA;
        if (lane < 17) sc[r0 * SCP + 32 + lane] = eA1 * invA;
        if (has1) {
            sc[r1 * SCP + lane] = eB0 * invB;
            if (lane < 17) sc[r1 * SCP + 32 + lane] = eB1 * invB;
        }
    }
    __syncthreads();

    // ---- PV as 4x4 reg-tiled smem GEMM: out[i][d] = sum_j p[i][j] * v[j][d]
    // tasks: 13 row-tiles x 8 dim-tiles = 104 (threads 104..127 idle)
    if (tid < 104) {
        const int ti = tid >> 3;          // 0..12
        const int tc = tid & 7;           // 0..7
        const int i0 = ti * 4;
        const int c0 = tc * 4;
        int ii[4];
#pragma unroll
        for (int r = 0; r < 4; ++r) ii[r] = (i0 + r < NTOK) ? i0 + r : NTOK - 1;

        float4 acc[4];
#pragma unroll
        for (int r = 0; r < 4; ++r) acc[r] = make_float4(0.f, 0.f, 0.f, 0.f);

#pragma unroll
        for (int jc = 0; jc < 12; ++jc) {
            const int j0 = jc * 4;
            float4 p4[4], v4[4];
#pragma unroll
            for (int r = 0; r < 4; ++r)
                p4[r] = *(const float4*)&sc[ii[r] * SCP + j0];
#pragma unroll
            for (int jj = 0; jj < 4; ++jj)
                v4[jj] = *(const float4*)&vs[(j0 + jj) * ROWP + c0];
#pragma unroll
            for (int r = 0; r < 4; ++r) {
                acc[r].x += p4[r].x * v4[0].x + p4[r].y * v4[1].x + p4[r].z * v4[2].x + p4[r].w * v4[3].x;
                acc[r].y += p4[r].x * v4[0].y + p4[r].y * v4[1].y + p4[r].z * v4[2].y + p4[r].w * v4[3].y;
                acc[r].z += p4[r].x * v4[0].z + p4[r].y * v4[1].z + p4[r].z * v4[2].z + p4[r].w * v4[3].z;
                acc[r].w += p4[r].x * v4[0].w + p4[r].y * v4[1].w + p4[r].z * v4[2].w + p4[r].w * v4[3].w;
            }
        }
        // tail j = 48
        {
            const float4 v4 = *(const float4*)&vs[48 * ROWP + c0];
#pragma unroll
            for (int r = 0; r < 4; ++r) {
                const float p = sc[ii[r] * SCP + 48];
                acc[r].x += p * v4.x;
                acc[r].y += p * v4.y;
                acc[r].z += p * v4.z;
                acc[r].w += p * v4.w;
            }
        }
        // store
#pragma unroll
        for (int r = 0; r < 4; ++r) {
            const int iiv = i0 + r;
            if (iiv < NTOK)
                *(float4*)&out[((size_t)b * NTOK + iiv) * CDIM + h * HDIM + c0] = acc[r];
        }
    }
}

// ---------------------------------------------------------------------------
// Launch: prep, dummy, GEMM, attn  (attn = ncu capture index 5)
// ---------------------------------------------------------------------------
extern "C" void kernel_launch(void* const* d_in, const int* in_sizes, int n_in,
                              void* d_out, int out_size)
{
    const float* hidden = (const float*)d_in[0];
    const float* mask   = (const float*)d_in[1];
    const float* wq     = (const float*)d_in[2];
    const float* bq     = (const float*)d_in[3];
    const float* wk     = (const float*)d_in[4];
    const float* bk     = (const float*)d_in[5];
    const float* wv     = (const float*)d_in[6];
    const float* bv     = (const float*)d_in[7];
    const float* btab   = (const float*)d_in[8];
    float* out = (float*)d_out;

    __half *ah, *wh;
    cudaGetSymbolAddress((void**)&ah, g_ah);
    cudaGetSymbolAddress((void**)&wh, g_wh);

    {
        const int ntask = NH8 + 3 * NW8;
        prep<<<(ntask + 255) / 256, 256>>>(hidden, wq, wk, wv, ah, wh);
    }

    dummy_k<<<1, 32>>>();

    cudaFuncSetAttribute(qkv_gemm_mma, cudaFuncAttributeMaxDynamicSharedMemorySize, GSMEM);
    dim3 g1(QKVCOLS / GBN, MTOT / GBM);   // 12 x 784
    qkv_gemm_mma<<<g1, 256, GSMEM>>>(ah, wh, bq, bk, bv);

    attn<<<BATCH * HEADS, 128>>>(mask, btab, out);
}

// round 16
// speedup vs baseline: 1.5369x; 1.5369x over previous
#include <cuda_runtime.h>
#include <cuda_fp16.h>
#include <cstdint>

// ---------------------------------------------------------------------------
// Problem constants
// ---------------------------------------------------------------------------
#define BATCH   2048
#define NTOK    49
#define HEADS   16
#define HDIM    32
#define CDIM    512
#define MW      64
#define MTOT    (BATCH*NTOK)   // 100352
#define QKVCOLS (3*CDIM)       // 1536

// head-major q/k/v: [b][h][n][d]
__device__ float g_q[(size_t)BATCH * HEADS * NTOK * HDIM];
__device__ float g_k[(size_t)BATCH * HEADS * NTOK * HDIM];
__device__ float g_v[(size_t)BATCH * HEADS * NTOK * HDIM];
__device__ __half g_ah[(size_t)MTOT * CDIM];     // hidden fp16
__device__ __half g_wh[(size_t)QKVCOLS * CDIM];  // weights fp16 (q|k|v rows)

// ---------------------------------------------------------------------------
// helpers
// ---------------------------------------------------------------------------
__device__ __forceinline__ uint32_t smem_u32(const void* p) {
    uint32_t a;
    asm("{ .reg .u64 t; cvta.to.shared.u64 t, %1; cvt.u32.u64 %0, t; }" : "=r"(a) : "l"(p));
    return a;
}
__device__ __forceinline__ void cp16(uint32_t saddr, const void* gaddr) {
    asm volatile("cp.async.cg.shared.global [%0], [%1], 16;" :: "r"(saddr), "l"(gaddr) : "memory");
}
__device__ __forceinline__ void cp_commit() {
    asm volatile("cp.async.commit_group;" ::: "memory");
}
template<int N> __device__ __forceinline__ void cp_wait() {
    asm volatile("cp.async.wait_group %0;" :: "n"(N) : "memory");
}
#define LDX4(d, addr) \
    asm volatile("ldmatrix.sync.aligned.m8n8.x4.shared.b16 {%0,%1,%2,%3}, [%4];" \
        : "=r"((d)[0]), "=r"((d)[1]), "=r"((d)[2]), "=r"((d)[3]) : "r"(addr))

__device__ __forceinline__ void mma_f16(float* c, const uint32_t* a, uint32_t b0, uint32_t b1) {
    asm volatile(
        "mma.sync.aligned.m16n8k16.row.col.f32.f16.f16.f32 "
        "{%0,%1,%2,%3}, {%4,%5,%6,%7}, {%8,%9}, {%0,%1,%2,%3};"
        : "+f"(c[0]), "+f"(c[1]), "+f"(c[2]), "+f"(c[3])
        : "r"(a[0]), "r"(a[1]), "r"(a[2]), "r"(a[3]), "r"(b0), "r"(b1));
}

// XOR swizzle for stride-32 q/k/v smem: float4 chunk c4 of row n lives at
// chunk (c4 ^ ((n>>2)&7)).  Rows with stride 4 (jj=4*tj+c) then spread over
// 8 bank groups instead of 2.
__device__ __forceinline__ int sw4(int n, int c4) {
    return n * 32 + (((c4) ^ ((n >> 2) & 7)) << 2);
}
__device__ __forceinline__ int sws(int n, int lane) {
    return n * 32 + ((((lane >> 2) ^ ((n >> 2) & 7)) << 2) | (lane & 3));
}

// ---------------------------------------------------------------------------
// Prep (single launch): fp32 -> fp16, hidden + all three weight matrices.
// ---------------------------------------------------------------------------
#define NH8 (MTOT * CDIM / 8)
#define NW8 32768

__global__ __launch_bounds__(256) void prep(
    const float* __restrict__ hidden,
    const float* __restrict__ wq, const float* __restrict__ wk,
    const float* __restrict__ wv,
    __half* __restrict__ ah, __half* __restrict__ wh)
{
    const int i = blockIdx.x * 256 + threadIdx.x;
    const float* src;
    __half* dst;
    int j;
    if (i < NH8) { src = hidden; dst = ah; j = i; }
    else {
        const int t = i - NH8;
        if (t >= 3 * NW8) return;
        const int m = t >> 15;
        j = t & (NW8 - 1);
        src = (m == 0) ? wq : (m == 1) ? wk : wv;
        dst = wh + (size_t)m * 512 * CDIM;
    }
    const float4 v0 = ((const float4*)src)[(size_t)j * 2];
    const float4 v1 = ((const float4*)src)[(size_t)j * 2 + 1];
    const float vv[8] = {v0.x, v0.y, v0.z, v0.w, v1.x, v1.y, v1.z, v1.w};
    __half h[8];
#pragma unroll
    for (int e = 0; e < 8; ++e) h[e] = __float2half_rn(vv[e]);
    *(uint4*)(dst + (size_t)j * 8) = *(const uint4*)h;
}

// steering no-op: [init,init,prep,dummy,gemm,attn] -> ncu -s 5 captures attn
__global__ void dummy_k() {}

// ---------------------------------------------------------------------------
// Tensor-core QKV GEMM — unchanged (head-major epilogue)
// ---------------------------------------------------------------------------
#define GBM 128
#define GBN 128
#define GBK 32
#define ASTR 40
#define STAGE_H (2 * GBM * ASTR)
#define OFF_AH 0
#define OFF_BH (GBM * ASTR)
#define NSTAGE 4
#define GSMEM  (NSTAGE * STAGE_H * 2)   // 81920 bytes

__global__ __launch_bounds__(256, 2) void qkv_gemm_mma(
    const __half* __restrict__ ah, const __half* __restrict__ wh,
    const float* __restrict__ bq, const float* __restrict__ bk2,
    const float* __restrict__ bv)
{
    extern __shared__ __align__(16) __half sm[];
    const uint32_t sb = smem_u32(sm);
    const int tid  = threadIdx.x;
    const int lane = tid & 31;
    const int w    = tid >> 5;
    const int m0   = blockIdx.y * GBM;
    const int jg0  = blockIdx.x * GBN;

    const int row = tid >> 1;
    const int c0  = (tid & 1) * 2;

    const __half* gah = ah + (size_t)m0 * CDIM;
    const __half* gwh = wh + (size_t)jg0 * CDIM;

    auto issue = [&](int it) {
        const uint32_t bufb = sb + (uint32_t)((it & 3) * STAGE_H) * 2;
        const size_t   gr = (size_t)row * CDIM + it * GBK;
        const uint32_t sr = (uint32_t)(row * ASTR) * 2;
#pragma unroll
        for (int c = 0; c < 2; ++c) {
            const int ch = c0 + c;
            cp16(bufb + OFF_AH * 2 + sr + ch * 16, gah + gr + ch * 8);
            cp16(bufb + OFF_BH * 2 + sr + ch * 16, gwh + gr + ch * 8);
        }
    };

    const int wm = (w & 1) * 64;
    const int wn = (w >> 1) * 32;
    const int lr = lane & 15;
    const int lc = (lane >> 4) * 8;

    float acc[4][4][4];
#pragma unroll
    for (int mi = 0; mi < 4; ++mi)
#pragma unroll
        for (int ni = 0; ni < 4; ++ni)
#pragma unroll
            for (int e = 0; e < 4; ++e) acc[mi][ni][e] = 0.f;

    auto compute = [&](int p) {
        const uint32_t bufb = sb + (uint32_t)(p * STAGE_H) * 2;
#pragma unroll
        for (int ks = 0; ks < 2; ++ks) {
            const int k0 = ks * 16;
            uint32_t AH[4][4], BH[2][4];
#pragma unroll
            for (int mi = 0; mi < 4; ++mi) {
                const uint32_t aoff = bufb + (uint32_t)((wm + mi * 16 + lr) * ASTR + k0 + lc) * 2;
                LDX4(AH[mi], aoff + OFF_AH * 2);
            }
#pragma unroll
            for (int nb = 0; nb < 2; ++nb) {
                const uint32_t boff = bufb + (uint32_t)((wn + nb * 16 + lr) * ASTR + k0 + lc) * 2;
                LDX4(BH[nb], boff + OFF_BH * 2);
            }
#pragma unroll
            for (int mi = 0; mi < 4; ++mi)
#pragma unroll
                for (int ni = 0; ni < 4; ++ni) {
                    const int nb = ni >> 1, sel = ni & 1;
                    mma_f16(acc[mi][ni], AH[mi], BH[nb][sel], BH[nb][sel + 2]);
                }
        }
    };

    issue(0); cp_commit();
    issue(1); cp_commit();
    issue(2); cp_commit();

#pragma unroll 1
    for (int it = 0; it < 13; ++it) {
        cp_wait<2>();
        __syncthreads();
        issue(it + 3);
        cp_commit();
        compute(it & 3);
    }
    cp_wait<2>(); __syncthreads(); compute(13 & 3);
    cp_wait<1>(); __syncthreads(); compute(14 & 3);
    cp_wait<0>(); __syncthreads(); compute(15 & 3);

    const int tsel = jg0 >> 9;
    float* gout = (tsel == 0) ? g_q : (tsel == 1) ? g_k : g_v;
    const float* bptr = (tsel == 0) ? bq : (tsel == 1) ? bk2 : bv;

#pragma unroll
    for (int ni = 0; ni < 4; ++ni) {
        const int jg = jg0 + wn + ni * 8 + 2 * (lane & 3);
        const int c  = jg & 511;
        const int h  = c >> 5;
        const int d  = c & 31;
        const float b0v = bptr[c];
        const float b1v = bptr[c + 1];
#pragma unroll
        for (int mi = 0; mi < 4; ++mi) {
#pragma unroll
            for (int half = 0; half < 2; ++half) {
                const int r = m0 + wm + mi * 16 + (lane >> 2) + half * 8;
                const int b = r / NTOK;
                const int n = r - b * NTOK;
                const size_t idx = (((size_t)(b * HEADS + h)) * NTOK + n) * HDIM + d;
                float2 o = { acc[mi][ni][half * 2 + 0] + b0v,
                             acc[mi][ni][half * 2 + 1] + b1v };
                *(float2*)&gout[idx] = o;
            }
        }
    }
}

// ---------------------------------------------------------------------------
// Attention per (window b, head h) — R13 structure, XOR-swizzled smem layout.
// ---------------------------------------------------------------------------
#define SCP  50

__global__ __launch_bounds__(128) void attn(
    const float* __restrict__ mask,
    const float* __restrict__ bias_table,
    float* __restrict__ out)
{
    __shared__ __align__(16) float qs[NTOK * 32];
    __shared__ __align__(16) float ks[NTOK * 32];
    __shared__ __align__(16) float vs[NTOK * 32];
    __shared__ float sc[NTOK * SCP];

    const int tid = threadIdx.x;
    const int bh  = blockIdx.x;
    const int b   = bh >> 4;
    const int h   = bh & 15;

    // ---- contiguous loads from head-major layout, swizzled STS
    const size_t hbase = (size_t)bh * NTOK * HDIM;
    const float* qg = g_q + hbase;
    const float* kg = g_k + hbase;
    const float* vg = g_v + hbase;
    for (int t = tid; t < NTOK * 8; t += 128) {
        const int n = t >> 3, f = t & 7;
        const int go = n * HDIM + f * 4;
        const int so = sw4(n, f);
        *(float4*)&qs[so] = *(const float4*)(qg + go);
        *(float4*)&ks[so] = *(const float4*)(kg + go);
        *(float4*)&vs[so] = *(const float4*)(vg + go);
    }
    __syncthreads();

    // ---- scores, 4x4 tiles (13x13 = 169 tasks), swizzled LDS
    const float* mrow = mask + (size_t)(b & (MW - 1)) * (NTOK * NTOK);
    for (int t = tid; t < 169; t += 128) {
        const int ti = t / 13, tj = t - ti * 13;
        const int i0 = ti * 4, j0 = tj * 4;
        int ii[4], jj[4];
#pragma unroll
        for (int r = 0; r < 4; ++r) {
            ii[r] = (i0 + r < NTOK) ? i0 + r : NTOK - 1;
            jj[r] = (j0 + r < NTOK) ? j0 + r : NTOK - 1;
        }
        float a[4][4];
#pragma unroll
        for (int r = 0; r < 4; ++r)
#pragma unroll
            for (int c = 0; c < 4; ++c) a[r][c] = 0.f;
#pragma unroll
        for (int dg = 0; dg < 8; ++dg) {
            float4 q4[4], k4[4];
#pragma unroll
            for (int r = 0; r < 4; ++r) {
                q4[r] = *(const float4*)&qs[sw4(ii[r], dg)];
                k4[r] = *(const float4*)&ks[sw4(jj[r], dg)];
            }
#pragma unroll
            for (int r = 0; r < 4; ++r)
#pragma unroll
                for (int c = 0; c < 4; ++c)
                    a[r][c] += q4[r].x * k4[c].x + q4[r].y * k4[c].y
                             + q4[r].z * k4[c].z + q4[r].w * k4[c].w;
        }
        const float sca = 0.17677669529663687f;   // 1/sqrt(32)
#pragma unroll
        for (int r = 0; r < 4; ++r) {
            const int iiv = i0 + r;
            if (iiv >= NTOK) break;
            const int iy = iiv / 7, ix = iiv - iy * 7;
#pragma unroll
            for (int c = 0; c < 4; ++c) {
                const int jjv = j0 + c;
                if (jjv >= NTOK) break;
                const int jy = jjv / 7, jx = jjv - jy * 7;
                const int ridx = (iy - jy + 6) * 13 + (ix - jx + 6);
                float s = a[r][c] * sca;
                s += bias_table[ridx * HEADS + h];
                s += mrow[iiv * NTOK + jjv];
                sc[iiv * SCP + jjv] = s;
            }
        }
    }
    __syncthreads();

    // ---- softmax + PV, two rows per warp pass (R13)
    const int warp = tid >> 5;
    const int lane = tid & 31;
    for (int pr = warp; pr < 25; pr += 4) {
        const int r0 = pr * 2;
        const int r1 = r0 + 1;
        const bool has1 = (r1 < NTOK);

        const float sA0 = sc[r0 * SCP + lane];
        const float sA1 = (lane < 17) ? sc[r0 * SCP + 32 + lane] : -3.4e38f;
        const float sB0 = has1 ? sc[r1 * SCP + lane] : 0.f;
        const float sB1 = (has1 && lane < 17) ? sc[r1 * SCP + 32 + lane] : -3.4e38f;

        float mA = fmaxf(sA0, sA1);
        float mB = fmaxf(sB0, sB1);
#pragma unroll
        for (int o = 16; o > 0; o >>= 1) {
            mA = fmaxf(mA, __shfl_xor_sync(0xffffffffu, mA, o));
            mB = fmaxf(mB, __shfl_xor_sync(0xffffffffu, mB, o));
        }
        const float eA0 = __expf(sA0 - mA);
        const float eA1 = (lane < 17) ? __expf(sA1 - mA) : 0.f;
        const float eB0 = __expf(sB0 - mB);
        const float eB1 = (has1 && lane < 17) ? __expf(sB1 - mB) : 0.f;
        float sumA = eA0 + eA1, sumB = eB0 + eB1;
#pragma unroll
        for (int o = 16; o > 0; o >>= 1) {
            sumA += __shfl_xor_sync(0xffffffffu, sumA, o);
            sumB += __shfl_xor_sync(0xffffffffu, sumB, o);
        }
        const float pA0 = eA0 * __frcp_rn(sumA);
        const float pA1 = eA1 * __frcp_rn(sumA);
        const float pB0 = eB0 * __frcp_rn(sumB);
        const float pB1 = eB1 * __frcp_rn(sumB);

        float accA = 0.f, accB = 0.f;
#pragma unroll
        for (int j = 0; j < NTOK; ++j) {
            const float vj = vs[sws(j, lane)];
            const float pa = (j < 32) ? __shfl_sync(0xffffffffu, pA0, j)
                                      : __shfl_sync(0xffffffffu, pA1, j - 32);
            const float pb = (j < 32) ? __shfl_sync(0xffffffffu, pB0, j)
                                      : __shfl_sync(0xffffffffu, pB1, j - 32);
            accA += pa * vj;
            accB += pb * vj;
        }
        out[((size_t)b * NTOK + r0) * CDIM + h * HDIM + lane] = accA;
        if (has1)
            out[((size_t)b * NTOK + r1) * CDIM + h * HDIM + lane] = accB;
    }
}

// ---------------------------------------------------------------------------
// Launch: prep, dummy, GEMM, attn  (attn = ncu capture index 5)
// ---------------------------------------------------------------------------
extern "C" void kernel_launch(void* const* d_in, const int* in_sizes, int n_in,
                              void* d_out, int out_size)
{
    const float* hidden = (const float*)d_in[0];
    const float* mask   = (const float*)d_in[1];
    const float* wq     = (const float*)d_in[2];
    const float* bq     = (const float*)d_in[3];
    const float* wk     = (const float*)d_in[4];
    const float* bk     = (const float*)d_in[5];
    const float* wv     = (const float*)d_in[6];
    const float* bv     = (const float*)d_in[7];
    const float* btab   = (const float*)d_in[8];
    float* out = (float*)d_out;

    __half *ah, *wh;
    cudaGetSymbolAddress((void**)&ah, g_ah);
    cudaGetSymbolAddress((void**)&wh, g_wh);

    {
        const int ntask = NH8 + 3 * NW8;
        prep<<<(ntask + 255) / 256, 256>>>(hidden, wq, wk, wv, ah, wh);
    }

    dummy_k<<<1, 32>>>();

    cudaFuncSetAttribute(qkv_gemm_mma, cudaFuncAttributeMaxDynamicSharedMemorySize, GSMEM);
    dim3 g1(QKVCOLS / GBN, MTOT / GBM);   // 12 x 784
    qkv_gemm_mma<<<g1, 256, GSMEM>>>(ah, wh, bq, bk, bv);

    attn<<<BATCH * HEADS, 128>>>(mask, btab, out);
}

// round 17
// speedup vs baseline: 2.7930x; 1.8173x over previous
#include <cuda_runtime.h>
#include <cuda_fp16.h>
#include <cstdint>

// ---------------------------------------------------------------------------
// Problem constants
// ---------------------------------------------------------------------------
#define BATCH   2048
#define NTOK    49
#define HEADS   16
#define HDIM    32
#define CDIM    512
#define MW      64
#define MTOT    (BATCH*NTOK)   // 100352
#define QKVCOLS (3*CDIM)       // 1536

// head-major fp16 q/k/v: [b][h][n][d]
__device__ __half g_qh[(size_t)BATCH * HEADS * NTOK * HDIM];
__device__ __half g_kh[(size_t)BATCH * HEADS * NTOK * HDIM];
__device__ __half g_vh[(size_t)BATCH * HEADS * NTOK * HDIM];
__device__ __half g_ah[(size_t)MTOT * CDIM];     // hidden fp16
__device__ __half g_wh[(size_t)QKVCOLS * CDIM];  // weights fp16 (q|k|v rows)
__device__ float  g_fbm[64 * 16 * 2404];         // fused bias+mask [bm][h][49*49 pad]

// ---------------------------------------------------------------------------
// helpers
// ---------------------------------------------------------------------------
__device__ __forceinline__ uint32_t smem_u32(const void* p) {
    uint32_t a;
    asm("{ .reg .u64 t; cvta.to.shared.u64 t, %1; cvt.u32.u64 %0, t; }" : "=r"(a) : "l"(p));
    return a;
}
__device__ __forceinline__ void cp16(uint32_t saddr, const void* gaddr) {
    asm volatile("cp.async.cg.shared.global [%0], [%1], 16;" :: "r"(saddr), "l"(gaddr) : "memory");
}
__device__ __forceinline__ void cp_commit() {
    asm volatile("cp.async.commit_group;" ::: "memory");
}
template<int N> __device__ __forceinline__ void cp_wait() {
    asm volatile("cp.async.wait_group %0;" :: "n"(N) : "memory");
}
#define LDX4(d, addr) \
    asm volatile("ldmatrix.sync.aligned.m8n8.x4.shared.b16 {%0,%1,%2,%3}, [%4];" \
        : "=r"((d)[0]), "=r"((d)[1]), "=r"((d)[2]), "=r"((d)[3]) : "r"(addr))
#define LDX4T(d, addr) \
    asm volatile("ldmatrix.sync.aligned.m8n8.x4.trans.shared.b16 {%0,%1,%2,%3}, [%4];" \
        : "=r"((d)[0]), "=r"((d)[1]), "=r"((d)[2]), "=r"((d)[3]) : "r"(addr))

__device__ __forceinline__ void mma_f16(float* c, const uint32_t* a, uint32_t b0, uint32_t b1) {
    asm volatile(
        "mma.sync.aligned.m16n8k16.row.col.f32.f16.f16.f32 "
        "{%0,%1,%2,%3}, {%4,%5,%6,%7}, {%8,%9}, {%0,%1,%2,%3};"
        : "+f"(c[0]), "+f"(c[1]), "+f"(c[2]), "+f"(c[3])
        : "r"(a[0]), "r"(a[1]), "r"(a[2]), "r"(a[3]), "r"(b0), "r"(b1));
}
__device__ __forceinline__ uint32_t packh2(float a, float b) {
    __half2 t = __floats2half2_rn(a, b);
    return *reinterpret_cast<uint32_t*>(&t);
}

// ---------------------------------------------------------------------------
// fuse bias_table + attention_mask per (mask_window, head): [64][16][2404]
// ---------------------------------------------------------------------------
__global__ __launch_bounds__(256) void fuse_bm(
    const float* __restrict__ mask, const float* __restrict__ btab)
{
    const int t = blockIdx.x * 256 + threadIdx.x;
    if (t >= 64 * 16 * 2401) return;
    const int bmh = t / 2401;
    const int e   = t - bmh * 2401;
    const int i = e / 49, j = e - (e / 49) * 49;
    const int h  = bmh & 15;
    const int bm = bmh >> 4;
    const int iy = i / 7, ix = i - iy * 7;
    const int jy = j / 7, jx = j - jy * 7;
    const int ridx = (iy - jy + 6) * 13 + (ix - jx + 6);
    g_fbm[(size_t)bmh * 2404 + e] = btab[ridx * HEADS + h] + mask[(size_t)bm * 2401 + e];
}

// ---------------------------------------------------------------------------
// Prep: fp32 -> fp16, hidden + all three weight matrices.
// ---------------------------------------------------------------------------
#define NH8 (MTOT * CDIM / 8)
#define NW8 32768

__global__ __launch_bounds__(256) void prep(
    const float* __restrict__ hidden,
    const float* __restrict__ wq, const float* __restrict__ wk,
    const float* __restrict__ wv,
    __half* __restrict__ ah, __half* __restrict__ wh)
{
    const int i = blockIdx.x * 256 + threadIdx.x;
    const float* src;
    __half* dst;
    int j;
    if (i < NH8) { src = hidden; dst = ah; j = i; }
    else {
        const int t = i - NH8;
        if (t >= 3 * NW8) return;
        const int m = t >> 15;
        j = t & (NW8 - 1);
        src = (m == 0) ? wq : (m == 1) ? wk : wv;
        dst = wh + (size_t)m * 512 * CDIM;
    }
    const float4 v0 = ((const float4*)src)[(size_t)j * 2];
    const float4 v1 = ((const float4*)src)[(size_t)j * 2 + 1];
    const float vv[8] = {v0.x, v0.y, v0.z, v0.w, v1.x, v1.y, v1.z, v1.w};
    __half h[8];
#pragma unroll
    for (int e = 0; e < 8; ++e) h[e] = __float2half_rn(vv[e]);
    *(uint4*)(dst + (size_t)j * 8) = *(const uint4*)h;
}

// ---------------------------------------------------------------------------
// Tensor-core QKV GEMM — epilogue now writes fp16 head-major q/k/v.
// ---------------------------------------------------------------------------
#define GBM 128
#define GBN 128
#define GBK 32
#define ASTR 40
#define STAGE_H (2 * GBM * ASTR)
#define OFF_AH 0
#define OFF_BH (GBM * ASTR)
#define NSTAGE 4
#define GSMEM  (NSTAGE * STAGE_H * 2)   // 81920 bytes

__global__ __launch_bounds__(256, 2) void qkv_gemm_mma(
    const __half* __restrict__ ah, const __half* __restrict__ wh,
    const float* __restrict__ bq, const float* __restrict__ bk2,
    const float* __restrict__ bv)
{
    extern __shared__ __align__(16) __half sm[];
    const uint32_t sb = smem_u32(sm);
    const int tid  = threadIdx.x;
    const int lane = tid & 31;
    const int w    = tid >> 5;
    const int m0   = blockIdx.y * GBM;
    const int jg0  = blockIdx.x * GBN;

    const int row = tid >> 1;
    const int c0  = (tid & 1) * 2;

    const __half* gah = ah + (size_t)m0 * CDIM;
    const __half* gwh = wh + (size_t)jg0 * CDIM;

    auto issue = [&](int it) {
        const uint32_t bufb = sb + (uint32_t)((it & 3) * STAGE_H) * 2;
        const size_t   gr = (size_t)row * CDIM + it * GBK;
        const uint32_t sr = (uint32_t)(row * ASTR) * 2;
#pragma unroll
        for (int c = 0; c < 2; ++c) {
            const int ch = c0 + c;
            cp16(bufb + OFF_AH * 2 + sr + ch * 16, gah + gr + ch * 8);
            cp16(bufb + OFF_BH * 2 + sr + ch * 16, gwh + gr + ch * 8);
        }
    };

    const int wm = (w & 1) * 64;
    const int wn = (w >> 1) * 32;
    const int lr = lane & 15;
    const int lc = (lane >> 4) * 8;

    float acc[4][4][4];
#pragma unroll
    for (int mi = 0; mi < 4; ++mi)
#pragma unroll
        for (int ni = 0; ni < 4; ++ni)
#pragma unroll
            for (int e = 0; e < 4; ++e) acc[mi][ni][e] = 0.f;

    auto compute = [&](int p) {
        const uint32_t bufb = sb + (uint32_t)(p * STAGE_H) * 2;
#pragma unroll
        for (int ks = 0; ks < 2; ++ks) {
            const int k0 = ks * 16;
            uint32_t AH[4][4], BH[2][4];
#pragma unroll
            for (int mi = 0; mi < 4; ++mi) {
                const uint32_t aoff = bufb + (uint32_t)((wm + mi * 16 + lr) * ASTR + k0 + lc) * 2;
                LDX4(AH[mi], aoff + OFF_AH * 2);
            }
#pragma unroll
            for (int nb = 0; nb < 2; ++nb) {
                const uint32_t boff = bufb + (uint32_t)((wn + nb * 16 + lr) * ASTR + k0 + lc) * 2;
                LDX4(BH[nb], boff + OFF_BH * 2);
            }
#pragma unroll
            for (int mi = 0; mi < 4; ++mi)
#pragma unroll
                for (int ni = 0; ni < 4; ++ni) {
                    const int nb = ni >> 1, sel = ni & 1;
                    mma_f16(acc[mi][ni], AH[mi], BH[nb][sel], BH[nb][sel + 2]);
                }
        }
    };

    issue(0); cp_commit();
    issue(1); cp_commit();
    issue(2); cp_commit();

#pragma unroll 1
    for (int it = 0; it < 13; ++it) {
        cp_wait<2>();
        __syncthreads();
        issue(it + 3);
        cp_commit();
        compute(it & 3);
    }
    cp_wait<2>(); __syncthreads(); compute(13 & 3);
    cp_wait<1>(); __syncthreads(); compute(14 & 3);
    cp_wait<0>(); __syncthreads(); compute(15 & 3);

    const int tsel = jg0 >> 9;
    __half* gout = (tsel == 0) ? g_qh : (tsel == 1) ? g_kh : g_vh;
    const float* bptr = (tsel == 0) ? bq : (tsel == 1) ? bk2 : bv;

#pragma unroll
    for (int ni = 0; ni < 4; ++ni) {
        const int jg = jg0 + wn + ni * 8 + 2 * (lane & 3);
        const int c  = jg & 511;
        const int h  = c >> 5;
        const int d  = c & 31;
        const float b0v = bptr[c];
        const float b1v = bptr[c + 1];
#pragma unroll
        for (int mi = 0; mi < 4; ++mi) {
#pragma unroll
            for (int half = 0; half < 2; ++half) {
                const int r = m0 + wm + mi * 16 + (lane >> 2) + half * 8;
                const int b = r / NTOK;
                const int n = r - b * NTOK;
                const size_t idx = (((size_t)(b * HEADS + h)) * NTOK + n) * HDIM + d;
                __half2 o = __floats2half2_rn(acc[mi][ni][half * 2 + 0] + b0v,
                                              acc[mi][ni][half * 2 + 1] + b1v);
                *(__half2*)&gout[idx] = o;
            }
        }
    }
}

// ---------------------------------------------------------------------------
// HMMA attention per (window b, head h): 128 threads, 4 warps.
// S = Q K^T via mma (N padded to 64), fragment softmax, PV via mma.
// ---------------------------------------------------------------------------
#define QSTR 40   // halves per smem row (ldmatrix conflict-free)

__global__ __launch_bounds__(128) void attn(float* __restrict__ out)
{
    __shared__ __align__(16) __half qs[64 * QSTR];
    __shared__ __align__(16) __half ks[64 * QSTR];
    __shared__ __align__(16) __half vs[64 * QSTR];
    __shared__ __align__(16) float  bm[2404];

    const int tid  = threadIdx.x;
    const int w    = tid >> 5;
    const int lane = tid & 31;
    const int gid  = lane >> 2;
    const int tig  = lane & 3;
    const int bh   = blockIdx.x;
    const int b    = bh >> 4;
    const int h    = bh & 15;

    // zero pad rows 49..63 (disjoint from data region: no pre-sync needed)
    {
        const uint4 z = make_uint4(0u, 0u, 0u, 0u);
        for (int t = tid; t < 225; t += 128) {
            const int a = t / 75, e = t - a * 75;
            __half* base = (a == 0) ? qs : (a == 1) ? ks : vs;
            ((uint4*)(base + 49 * QSTR))[e] = z;
        }
    }
    // load q/k/v rows 0..48 (32 halves/row = 4 uint4)
    {
        const size_t gb = (size_t)bh * NTOK * HDIM;
        for (int t = tid; t < 3 * 196; t += 128) {
            const int a = t / 196, e = t - a * 196;
            const int n = e >> 2, f = e & 3;
            const __half* src = ((a == 0) ? g_qh : (a == 1) ? g_kh : g_vh) + gb + n * HDIM + f * 8;
            __half* dst = ((a == 0) ? qs : (a == 1) ? ks : vs) + n * QSTR + f * 8;
            *(uint4*)dst = *(const uint4*)src;
        }
    }
    // load fused bias+mask tile (2401 floats, padded to 2404)
    {
        const float4* src = (const float4*)(g_fbm + (size_t)(((b & 63) << 4) + h) * 2404);
        for (int t = tid; t < 601; t += 128)
            ((float4*)bm)[t] = src[t];
    }
    __syncthreads();

    const uint32_t qsb = smem_u32(qs);
    const uint32_t ksb = smem_u32(ks);
    const uint32_t vsb = smem_u32(vs);
    const int lr = lane & 15;
    const int lc = (lane >> 4) * 8;

    // ---- scores: S[64x64], warp w owns rows 16w..16w+15
    uint32_t A0[2][4];
    LDX4(A0[0], qsb + (uint32_t)((16 * w + lr) * QSTR + 0  + lc) * 2);
    LDX4(A0[1], qsb + (uint32_t)((16 * w + lr) * QSTR + 16 + lc) * 2);

    float S[8][4];
#pragma unroll
    for (int t = 0; t < 8; ++t)
#pragma unroll
        for (int e = 0; e < 4; ++e) S[t][e] = 0.f;

#pragma unroll
    for (int nb2 = 0; nb2 < 4; ++nb2) {
        uint32_t B0[2][4];
        LDX4(B0[0], ksb + (uint32_t)((nb2 * 16 + lr) * QSTR + 0  + lc) * 2);
        LDX4(B0[1], ksb + (uint32_t)((nb2 * 16 + lr) * QSTR + 16 + lc) * 2);
#pragma unroll
        for (int sel = 0; sel < 2; ++sel) {
            const int t = nb2 * 2 + sel;
            mma_f16(S[t], A0[0], B0[0][sel], B0[0][sel + 2]);
            mma_f16(S[t], A0[1], B0[1][sel], B0[1][sel + 2]);
        }
    }

    // ---- fragment epilogue: scale + fused bias/mask, col mask j>=49
    const float sca = 0.17677669529663687f;
    const int iA = 16 * w + gid;
    const int iB = iA + 8;
    const int iAo = ((iA < 49) ? iA : 0) * 49;
    const int iBo = ((iB < 49) ? iB : 0) * 49;

    float mA = -3.4e38f, mB = -3.4e38f;
#pragma unroll
    for (int t = 0; t < 8; ++t) {
        const int j0 = 8 * t + 2 * tig;
        const bool v0 = (j0 < 49), v1 = (j0 + 1 < 49);
        S[t][0] = v0 ? (S[t][0] * sca + bm[iAo + j0])     : -1e30f;
        S[t][1] = v1 ? (S[t][1] * sca + bm[iAo + j0 + 1]) : -1e30f;
        S[t][2] = v0 ? (S[t][2] * sca + bm[iBo + j0])     : -1e30f;
        S[t][3] = v1 ? (S[t][3] * sca + bm[iBo + j0 + 1]) : -1e30f;
        mA = fmaxf(mA, fmaxf(S[t][0], S[t][1]));
        mB = fmaxf(mB, fmaxf(S[t][2], S[t][3]));
    }
    mA = fmaxf(mA, __shfl_xor_sync(0xffffffffu, mA, 1));
    mA = fmaxf(mA, __shfl_xor_sync(0xffffffffu, mA, 2));
    mB = fmaxf(mB, __shfl_xor_sync(0xffffffffu, mB, 1));
    mB = fmaxf(mB, __shfl_xor_sync(0xffffffffu, mB, 2));

    float sumA = 0.f, sumB = 0.f;
#pragma unroll
    for (int t = 0; t < 8; ++t) {
        S[t][0] = __expf(S[t][0] - mA);
        S[t][1] = __expf(S[t][1] - mA);
        S[t][2] = __expf(S[t][2] - mB);
        S[t][3] = __expf(S[t][3] - mB);
        sumA += S[t][0] + S[t][1];
        sumB += S[t][2] + S[t][3];
    }
    sumA += __shfl_xor_sync(0xffffffffu, sumA, 1);
    sumA += __shfl_xor_sync(0xffffffffu, sumA, 2);
    sumB += __shfl_xor_sync(0xffffffffu, sumB, 1);
    sumB += __shfl_xor_sync(0xffffffffu, sumB, 2);
    const float invA = __frcp_rn(sumA);
    const float invB = __frcp_rn(sumB);
#pragma unroll
    for (int t = 0; t < 8; ++t) {
        S[t][0] *= invA; S[t][1] *= invA;
        S[t][2] *= invB; S[t][3] *= invB;
    }

    // ---- PV: O[16x32] per warp = P[16x64] x V[64x32]
    float O[4][4];
#pragma unroll
    for (int dt = 0; dt < 4; ++dt)
#pragma unroll
        for (int e = 0; e < 4; ++e) O[dt][e] = 0.f;

#pragma unroll
    for (int ks2 = 0; ks2 < 4; ++ks2) {
        uint32_t Pf[4];
        Pf[0] = packh2(S[2 * ks2][0],     S[2 * ks2][1]);
        Pf[1] = packh2(S[2 * ks2][2],     S[2 * ks2][3]);
        Pf[2] = packh2(S[2 * ks2 + 1][0], S[2 * ks2 + 1][1]);
        Pf[3] = packh2(S[2 * ks2 + 1][2], S[2 * ks2 + 1][3]);

        uint32_t Vb[2][4];
        LDX4T(Vb[0], vsb + (uint32_t)((ks2 * 16 + lr) * QSTR + 0  + lc) * 2);
        LDX4T(Vb[1], vsb + (uint32_t)((ks2 * 16 + lr) * QSTR + 16 + lc) * 2);

        mma_f16(O[0], Pf, Vb[0][0], Vb[0][1]);
        mma_f16(O[1], Pf, Vb[0][2], Vb[0][3]);
        mma_f16(O[2], Pf, Vb[1][0], Vb[1][1]);
        mma_f16(O[3], Pf, Vb[1][2], Vb[1][3]);
    }

    // ---- store (rows < 49 only)
#pragma unroll
    for (int dt = 0; dt < 4; ++dt) {
        const int d = 8 * dt + 2 * tig;
        if (iA < NTOK) {
            float2 o = { O[dt][0], O[dt][1] };
            *(float2*)&out[((size_t)b * NTOK + iA) * CDIM + h * HDIM + d] = o;
        }
        if (iB < NTOK) {
            float2 o = { O[dt][2], O[dt][3] };
            *(float2*)&out[((size_t)b * NTOK + iB) * CDIM + h * HDIM + d] = o;
        }
    }
}

// ---------------------------------------------------------------------------
// Launch: fuse_bm, prep, GEMM, attn  (2 harness inits => attn at ncu idx 5)
// ---------------------------------------------------------------------------
extern "C" void kernel_launch(void* const* d_in, const int* in_sizes, int n_in,
                              void* d_out, int out_size)
{
    const float* hidden = (const float*)d_in[0];
    const float* mask   = (const float*)d_in[1];
    const float* wq     = (const float*)d_in[2];
    const float* bq     = (const float*)d_in[3];
    const float* wk     = (const float*)d_in[4];
    const float* bk     = (const float*)d_in[5];
    const float* wv     = (const float*)d_in[6];
    const float* bv     = (const float*)d_in[7];
    const float* btab   = (const float*)d_in[8];
    float* out = (float*)d_out;

    __half *ah, *wh;
    cudaGetSymbolAddress((void**)&ah, g_ah);
    cudaGetSymbolAddress((void**)&wh, g_wh);

    fuse_bm<<<(64 * 16 * 2401 + 255) / 256, 256>>>(mask, btab);

    {
        const int ntask = NH8 + 3 * NW8;
        prep<<<(ntask + 255) / 256, 256>>>(hidden, wq, wk, wv, ah, wh);
    }

    cudaFuncSetAttribute(qkv_gemm_mma, cudaFuncAttributeMaxDynamicSharedMemorySize, GSMEM);
    dim3 g1(QKVCOLS / GBN, MTOT / GBM);   // 12 x 784
    qkv_gemm_mma<<<g1, 256, GSMEM>>>(ah, wh, bq, bk, bv);

    attn<<<BATCH * HEADS, 128>>>(out);
}